// round 14
// baseline (speedup 1.0000x reference)
#include <cuda_runtime.h>
#include <cuda_fp16.h>
#include <math.h>
#include <stdint.h>

#define BATCH 8
#define CDIM 192
#define C3 576
#define HEADS 8
#define CHH 24
#define NPIX 16384
#define IMW 128

// ---------------- scratch (device globals; allocation-free rule) ------------
__device__ __half g_qkv1[BATCH * C3 * NPIX];     // 1x1-conv output, fp16
__device__ __half g_qkvh[BATCH * C3 * NPIX];     // dwconv output (q,k,v), fp16
__device__ float g_gram[BATCH * HEADS * CHH * CHH];
__device__ float g_nq[BATCH * CDIM];
__device__ float g_nk[BATCH * CDIM];
__device__ __half g_wq[C3 * CDIM];
__device__ __half g_weff[BATCH * CDIM * CDIM];

#define MMA_F16(d, a, bb) \
    asm volatile("mma.sync.aligned.m16n8k16.row.col.f32.f16.f16.f32 " \
        "{%0,%1,%2,%3}, {%4,%5,%6,%7}, {%8,%9}, {%0,%1,%2,%3};" \
        : "+f"((d)[0]), "+f"((d)[1]), "+f"((d)[2]), "+f"((d)[3]) \
        : "r"((a)[0]), "r"((a)[1]), "r"((a)[2]), "r"((a)[3]), \
          "r"((bb)[0]), "r"((bb)[1]))

#define LDSM_X4(r0, r1, r2, r3, addr) \
    asm volatile("ldmatrix.sync.aligned.m8n8.x4.shared.b16 {%0,%1,%2,%3}, [%4];" \
        : "=r"(r0), "=r"(r1), "=r"(r2), "=r"(r3) : "r"(addr))

__device__ __forceinline__ uint32_t pack_h2(__half a, __half b) {
    return ((uint32_t)__half_as_ushort(b) << 16) | __half_as_ushort(a);
}
__device__ __forceinline__ uint32_t smem_u32(const void* p) {
    uint32_t a;
    asm("{ .reg .u64 t; cvta.to.shared.u64 t, %1; cvt.u32.u64 %0, t; }"
        : "=r"(a) : "l"(p));
    return a;
}
__device__ __forceinline__ void cp_async16(uint32_t dst, const void* src) {
    asm volatile("cp.async.cg.shared.global [%0], [%1], 16;" :: "r"(dst), "l"(src));
}

// ---------------------------------------------------------------------------
// B staging + epilogue helpers (fp32 / fp16 variants)
// ---------------------------------------------------------------------------
#define LDAE 200
#define LDBF 200

__device__ __forceinline__ void stage_b(__half* Bs, const float* Xp, int n0, int id) {
    int kr = (id >> 4) * 2, nc = (id & 15) * 4;
    float4 r0 = *reinterpret_cast<const float4*>(&Xp[(long long)kr * NPIX + n0 + nc]);
    float4 r1 = *reinterpret_cast<const float4*>(&Xp[(long long)(kr + 1) * NPIX + n0 + nc]);
    float e0[4] = {r0.x, r0.y, r0.z, r0.w};
    float e1[4] = {r1.x, r1.y, r1.z, r1.w};
#pragma unroll
    for (int i = 0; i < 4; ++i)
        *reinterpret_cast<uint32_t*>(&Bs[(nc + i) * LDBF + kr]) =
            pack_h2(__float2half(e0[i]), __float2half(e1[i]));
}
__device__ __forceinline__ void stage_b(__half* Bs, const __half* Xp, int n0, int id) {
    int kr = (id >> 4) * 2, nc = (id & 15) * 4;
    uint2 r0 = *reinterpret_cast<const uint2*>(&Xp[(long long)kr * NPIX + n0 + nc]);
    uint2 r1 = *reinterpret_cast<const uint2*>(&Xp[(long long)(kr + 1) * NPIX + n0 + nc]);
    *reinterpret_cast<uint32_t*>(&Bs[(nc + 0) * LDBF + kr]) = __byte_perm(r0.x, r1.x, 0x5410);
    *reinterpret_cast<uint32_t*>(&Bs[(nc + 1) * LDBF + kr]) = __byte_perm(r0.x, r1.x, 0x7632);
    *reinterpret_cast<uint32_t*>(&Bs[(nc + 2) * LDBF + kr]) = __byte_perm(r0.y, r1.y, 0x5410);
    *reinterpret_cast<uint32_t*>(&Bs[(nc + 3) * LDBF + kr]) = __byte_perm(r0.y, r1.y, 0x7632);
}
__device__ __forceinline__ void st_out(float* p, float a, float b) {
    *reinterpret_cast<float2*>(p) = make_float2(a, b);
}
__device__ __forceinline__ void st_out(__half* p, float a, float b) {
    *reinterpret_cast<uint32_t*>(p) = pack_h2(__float2half(a), __float2half(b));
}

// ---------------------------------------------------------------------------
// HMMA GEMM, B-panel-stationary (round-11 winner), templated on B/out dtype.
// ---------------------------------------------------------------------------
#define A_BYTES (192 * LDAE * 2)
#define SMEM_GEMM (A_BYTES + 64 * LDBF * 2)   // 102400 bytes

template <typename TB, typename TO>
__global__ __launch_bounds__(256, 2)
void gemm_mma(const __half* __restrict__ W, long long wstride,
              const TB* __restrict__ X, long long xstride,
              TO* __restrict__ Y, long long ystride, int NO)
{
    extern __shared__ __half smem[];
    __half* Ah = smem;
    __half* Bs = smem + 192 * LDAE;

    const int b = blockIdx.y;
    const int n0 = blockIdx.x * 64;
    const __half* Wp = W + (long long)b * wstride;
    const TB* Xp = X + (long long)b * xstride;
    TO* Yp = Y + (long long)b * ystride;

    const int tid = threadIdx.x;
    const int lane = tid & 31;
    const int wid = tid >> 5;
    const int wm = wid & 3;
    const int wn = wid >> 2;

    const uint32_t a_base = smem_u32(Ah);
    const uint32_t b_base = smem_u32(Bs);

    {
#pragma unroll
        for (int c = 0; c < 18; ++c) {
            int ch = c * 256 + tid;
            int row = ch / 24, col = ch % 24;
            uint32_t doff = (uint32_t)(row * LDAE + col * 8) * 2u;
            cp_async16(a_base + doff, Wp + (long long)row * CDIM + col * 8);
        }
        asm volatile("cp.async.commit_group;");
    }
#pragma unroll
    for (int it = 0; it < 6; ++it)
        stage_b(Bs, Xp, n0, it * 256 + tid);

    const int lg = lane >> 3, lr = lane & 7;
    uint32_t a_row[3];
#pragma unroll
    for (int mi = 0; mi < 3; ++mi) {
        int row = wm * 48 + mi * 16 + (lg & 1) * 8 + lr;
        a_row[mi] = a_base + (uint32_t)(row * LDAE + (lg >> 1) * 8) * 2u;
    }
    uint32_t b_row[2];
#pragma unroll
    for (int nj = 0; nj < 2; ++nj) {
        int n = wn * 32 + (nj * 2 + (lg >> 1)) * 8 + lr;
        b_row[nj] = b_base + (uint32_t)(n * LDBF + (lg & 1) * 8) * 2u;
    }

    for (int op = 0; op < NO; ++op) {
        asm volatile("cp.async.wait_group 0;");
        __syncthreads();

        float acc[3][4][4];
#pragma unroll
        for (int mi = 0; mi < 3; ++mi)
#pragma unroll
            for (int ni = 0; ni < 4; ++ni)
#pragma unroll
                for (int q = 0; q < 4; ++q) acc[mi][ni][q] = 0.f;

#pragma unroll
        for (int ks = 0; ks < 12; ++ks) {
            const uint32_t koff = (uint32_t)(ks * 16) * 2u;
            uint32_t fa[3][4], fb[4][2];
#pragma unroll
            for (int mi = 0; mi < 3; ++mi)
                LDSM_X4(fa[mi][0], fa[mi][1], fa[mi][2], fa[mi][3],
                        a_row[mi] + koff);
#pragma unroll
            for (int nj = 0; nj < 2; ++nj)
                LDSM_X4(fb[2 * nj][0], fb[2 * nj][1], fb[2 * nj + 1][0], fb[2 * nj + 1][1],
                        b_row[nj] + koff);
#pragma unroll
            for (int mi = 0; mi < 3; ++mi)
#pragma unroll
                for (int ni = 0; ni < 4; ++ni)
                    MMA_F16(acc[mi][ni], fa[mi], fb[ni]);
        }

        __syncthreads();

        if (op + 1 < NO) {
            const __half* Wn = Wp + (long long)(op + 1) * 192 * CDIM;
#pragma unroll
            for (int c = 0; c < 18; ++c) {
                int ch = c * 256 + tid;
                int row = ch / 24, col = ch % 24;
                uint32_t doff = (uint32_t)(row * LDAE + col * 8) * 2u;
                cp_async16(a_base + doff, Wn + (long long)row * CDIM + col * 8);
            }
            asm volatile("cp.async.commit_group;");
        }

        const int ob = op * 192;
#pragma unroll
        for (int mi = 0; mi < 3; ++mi) {
            int r = ob + wm * 48 + mi * 16 + (lane >> 2);
#pragma unroll
            for (int ni = 0; ni < 4; ++ni) {
                int c = n0 + wn * 32 + ni * 8 + (lane & 3) * 2;
                st_out(&Yp[(long long)r * NPIX + c], acc[mi][ni][0], acc[mi][ni][1]);
                st_out(&Yp[(long long)(r + 8) * NPIX + c], acc[mi][ni][2], acc[mi][ni][3]);
            }
        }
    }
}

// ---------------------------------------------------------------------------
// Weight prep (also zeroes gram/norm accumulators when base==0)
// ---------------------------------------------------------------------------
__global__ void prep_wqkv_kernel(const float* __restrict__ W, int base)
{
    int lin = blockIdx.x * blockDim.x + threadIdx.x;
    if (base == 0) {
        if (lin < BATCH * HEADS * CHH * CHH) g_gram[lin] = 0.f;
        if (lin < BATCH * CDIM) { g_nq[lin] = 0.f; g_nk[lin] = 0.f; }
    }
    int idx = base + lin;
    if (idx >= C3 * CDIM) return;
    g_wq[idx] = __float2half(W[idx]);
}

// ---------------------------------------------------------------------------
// 3x3 depthwise conv, padding 1; fp16 in, fp16 out (all channels); 8 px/thread
// ---------------------------------------------------------------------------
__global__ void dwconv_kernel(const __half* __restrict__ in,
                              const float* __restrict__ wdw,
                              __half* __restrict__ outh)
{
    long long idx = (long long)blockIdx.x * blockDim.x + threadIdx.x;
    if (idx >= (long long)BATCH * C3 * (NPIX / 8)) return;
    const int n8 = (int)(idx & (NPIX / 8 - 1));
    const int t = (int)(idx >> 11);
    const int ch = t % C3;
    const int b = t / C3;
    const int y = n8 >> 4;
    const int x0 = (n8 & 15) * 8;
    const float* w = wdw + ch * 9;
    const __half* p = in + ((long long)b * C3 + ch) * NPIX;

    float o[8];
#pragma unroll
    for (int i = 0; i < 8; ++i) o[i] = 0.f;
#pragma unroll
    for (int r = 0; r < 3; ++r) {
        int yy = y + r - 1;
        if (yy < 0 || yy > IMW - 1) continue;
        const __half* row = p + yy * IMW;
        uint4 cc = *reinterpret_cast<const uint4*>(&row[x0]);
        float2 p0 = __half22float2(*reinterpret_cast<const __half2*>(&cc.x));
        float2 p1 = __half22float2(*reinterpret_cast<const __half2*>(&cc.y));
        float2 p2 = __half22float2(*reinterpret_cast<const __half2*>(&cc.z));
        float2 p3 = __half22float2(*reinterpret_cast<const __half2*>(&cc.w));
        float e[10];
        e[0] = (x0 > 0) ? __half2float(row[x0 - 1]) : 0.f;
        e[1] = p0.x; e[2] = p0.y; e[3] = p1.x; e[4] = p1.y;
        e[5] = p2.x; e[6] = p2.y; e[7] = p3.x; e[8] = p3.y;
        e[9] = (x0 < IMW - 8) ? __half2float(row[x0 + 8]) : 0.f;
        float w0 = w[r * 3], w1 = w[r * 3 + 1], w2 = w[r * 3 + 2];
#pragma unroll
        for (int i = 0; i < 8; ++i)
            o[i] += w0 * e[i] + w1 * e[i + 1] + w2 * e[i + 2];
    }

    __half* op = outh + ((long long)b * C3 + ch) * NPIX + y * IMW + x0;
    uint4 res;
    res.x = pack_h2(__float2half(o[0]), __float2half(o[1]));
    res.y = pack_h2(__float2half(o[2]), __float2half(o[3]));
    res.z = pack_h2(__float2half(o[4]), __float2half(o[5]));
    res.w = pack_h2(__float2half(o[6]), __float2half(o[7]));
    *reinterpret_cast<uint4*>(op) = res;
}

// ---------------------------------------------------------------------------
// Gram + fused norms (reads fp16 q/k, fp32 feat; fp32 compute/accumulate)
// ---------------------------------------------------------------------------
__global__ void gram_kernel(const float* __restrict__ feat)
{
    __shared__ float QF[4][CHH][64];
    __shared__ float KF[4][CHH][64];

    const int bh = blockIdx.y;
    const int b = bh >> 3, hd = bh & 7;
    const int n0 = blockIdx.x * 1024;
    const int t = threadIdx.x;
    const int g = t >> 6, l = t & 63;
    const int li = l >> 3, lj = l & 7;
    const int i0 = li * 3, j0 = lj * 3;

    const __half* qbase = g_qkvh + ((long long)b * C3 + hd * CHH) * NPIX;
    const __half* kbase = g_qkvh + ((long long)b * C3 + CDIM + hd * CHH) * NPIX;
    const float* fbase = feat + ((long long)b * CDIM + hd * CHH) * NPIX;

    float acc[3][3];
#pragma unroll
    for (int a = 0; a < 3; ++a)
#pragma unroll
        for (int cc = 0; cc < 3; ++cc) acc[a][cc] = 0.f;
    float nqp = 0.f, nkp = 0.f;

    for (int s = 0; s < 1024; s += 256) {
        const int nb = n0 + s + g * 64;
        for (int e = l; e < CHH * 64; e += 64) {
            int i = e >> 6, nn = e & 63;
            long long off = (long long)i * NPIX + nb + nn;
            float fv = fbase[off];
            QF[g][i][nn] = __half2float(qbase[off]) * fv;
            KF[g][i][nn] = __half2float(kbase[off]) * fv;
        }
        __syncthreads();
#pragma unroll 4
        for (int it = 0; it < 64; ++it) {
            int nn = (it + l) & 63;
            float q0 = QF[g][i0 + 0][nn];
            float q1 = QF[g][i0 + 1][nn];
            float q2 = QF[g][i0 + 2][nn];
            float k0 = KF[g][j0 + 0][nn];
            float k1 = KF[g][j0 + 1][nn];
            float k2 = KF[g][j0 + 2][nn];
            acc[0][0] += q0 * k0; acc[0][1] += q0 * k1; acc[0][2] += q0 * k2;
            acc[1][0] += q1 * k0; acc[1][1] += q1 * k1; acc[1][2] += q1 * k2;
            acc[2][0] += q2 * k0; acc[2][1] += q2 * k1; acc[2][2] += q2 * k2;
        }
        if (l < CHH) {
#pragma unroll 4
            for (int it = 0; it < 64; ++it) {
                int nn = (it + l) & 63;
                float qv = QF[g][l][nn]; nqp += qv * qv;
                float kv = KF[g][l][nn]; nkp += kv * kv;
            }
        }
        __syncthreads();
    }

#pragma unroll
    for (int a = 0; a < 3; ++a)
#pragma unroll
        for (int cc = 0; cc < 3; ++cc)
            atomicAdd(&g_gram[(bh * CHH + i0 + a) * CHH + j0 + cc], acc[a][cc]);
    if (l < CHH) {
        atomicAdd(&g_nq[b * CDIM + hd * CHH + l], nqp);
        atomicAdd(&g_nk[b * CDIM + hd * CHH + l], nkp);
    }
}

// ---------------------------------------------------------------------------
// Softmax + W_eff = W_proj @ A_blockdiag, emitted fp16 [192][192]
// ---------------------------------------------------------------------------
__global__ void softmax_weff_kernel(const float* __restrict__ temp,
                                    const float* __restrict__ Wp)
{
    const int b = blockIdx.x;
    const int t = threadIdx.x;            // 384
    __shared__ float A[HEADS][CHH][CHH];
    __shared__ float qinv[CDIM], kinv[CDIM];

    if (t < CDIM) {
        qinv[t] = 1.0f / fmaxf(sqrtf(g_nq[b * CDIM + t]), 1e-12f);
    } else if (t < 2 * CDIM) {
        int c = t - CDIM;
        kinv[c] = 1.0f / fmaxf(sqrtf(g_nk[b * CDIM + c]), 1e-12f);
    }
    __syncthreads();

    if (t < CDIM) {
        const int hd = t / CHH, i = t % CHH;
        const float tp = temp[hd];
        const float qi = qinv[hd * CHH + i];
        float row[CHH];
        float m = -1e30f;
#pragma unroll
        for (int j = 0; j < CHH; ++j) {
            float v = g_gram[((b * HEADS + hd) * CHH + i) * CHH + j]
                      * tp * qi * kinv[hd * CHH + j];
            row[j] = v;
            m = fmaxf(m, v);
        }
        float ssum = 0.f;
#pragma unroll
        for (int j = 0; j < CHH; ++j) { row[j] = expf(row[j] - m); ssum += row[j]; }
        float inv = 1.0f / ssum;
#pragma unroll
        for (int j = 0; j < CHH; ++j) A[hd][i][j] = row[j] * inv;
    }
    __syncthreads();

    for (int idx = t; idx < CDIM * CDIM; idx += 384) {
        const int o = idx / CDIM, cc = idx % CDIM;
        const int hd = cc / CHH, j = cc % CHH;
        float s = 0.f;
#pragma unroll
        for (int i = 0; i < CHH; ++i)
            s += Wp[o * CDIM + hd * CHH + i] * A[hd][i][j];
        g_weff[(long long)b * CDIM * CDIM + idx] = __float2half(s);
    }
}

// ---------------------------------------------------------------------------
extern "C" void kernel_launch(void* const* d_in, const int* in_sizes, int n_in,
                              void* d_out, int out_size)
{
    (void)in_sizes; (void)n_in; (void)out_size;
    const float* x     = (const float*)d_in[0];
    const float* feat  = (const float*)d_in[1];
    const float* Wqkv  = (const float*)d_in[2];
    const float* Wdw   = (const float*)d_in[3];
    const float* Wproj = (const float*)d_in[4];
    const float* temp  = (const float*)d_in[5];
    float* out = (float*)d_out;

    __half *qkv1, *qkvh, *wq, *wf;
    cudaGetSymbolAddress((void**)&qkv1, g_qkv1);
    cudaGetSymbolAddress((void**)&qkvh, g_qkvh);
    cudaGetSymbolAddress((void**)&wq, g_wq);
    cudaGetSymbolAddress((void**)&wf, g_weff);

    static int smem_set = 0;
    if (!smem_set) {
        cudaFuncSetAttribute(gemm_mma<float, __half>,
                             cudaFuncAttributeMaxDynamicSharedMemorySize, SMEM_GEMM);
        cudaFuncSetAttribute(gemm_mma<__half, float>,
                             cudaFuncAttributeMaxDynamicSharedMemorySize, SMEM_GEMM);
        smem_set = 1;
    }

    const int HALF_W = C3 * CDIM / 2;

    // 1,2) weight prep (+ accumulator zeroing)
    prep_wqkv_kernel<<<(HALF_W + 255) / 256, 256>>>(Wqkv, 0);
    prep_wqkv_kernel<<<(HALF_W + 255) / 256, 256>>>(Wqkv, HALF_W);

    // 3) qkv1 = W_qkv @ x  (fp32 B in, fp16 out; B-stationary, 3 o-panels)
    gemm_mma<float, __half><<<dim3(NPIX / 64, BATCH), 256, SMEM_GEMM>>>(
        wq, 0LL, x, (long long)CDIM * NPIX, qkv1, (long long)C3 * NPIX, 3);

    // 4) depthwise conv (fp16 -> fp16, all channels)   [ncu slot 4]
    {
        long long total = (long long)BATCH * C3 * (NPIX / 8);
        dwconv_kernel<<<(int)((total + 255) / 256), 256>>>(qkv1, Wdw, qkvh);
    }

    // 5) Gram + norms (fp16 q/k)
    gram_kernel<<<dim3(16, BATCH * HEADS), 256>>>(feat);

    // 6) softmax + W_eff (fp16)
    softmax_weff_kernel<<<BATCH, 384>>>(temp, Wproj);

    // 7) out = W_eff @ v  (fp16 B in, fp32 out)
    gemm_mma<__half, float><<<dim3(NPIX / 64, BATCH), 256, SMEM_GEMM>>>(
        wf, (long long)CDIM * CDIM,
        qkvh + (long long)2 * CDIM * NPIX, (long long)C3 * NPIX,
        out, (long long)CDIM * NPIX, 1);
}